// round 2
// baseline (speedup 1.0000x reference)
#include <cuda_runtime.h>

#define T_STEPS 36
#define FEAT 36
#define HID 64
#define NG 256
#define K_IH 108
#define BM 128
#define NTHR 1024

// SMEM layout (float offsets)
#define S_OFF    0        // S[128][108]  : x_c | gamma | m
#define H_OFF    13824    // h[2][128][64]
#define DATE_OFF 30208    // date[128][10]
#define WR_OFF   31488    // Wr[74][36]  (k-major)
#define WD_OFF   34152    // Wd[36][36]  (k-major)
#define BREG_OFF 35448
#define BDEC_OFF 35484
#define EM_OFF   35520    // year(4) month(24) day(96) hour(72)
#define BP_OFF   35716    // permuted b_ih+b_hh [256]
#define NUM_OFF  35972
#define DEN_OFF  36008
#define SMEM_FLOATS 36044
#define SMEM_BYTES (SMEM_FLOATS * 4)

// Global scratch (no allocation allowed) — permuted gate weights + loss accumulators
__device__ __align__(16) float g_Wp_ih[K_IH * NG];  // [k][4*j+g]
__device__ __align__(16) float g_Wp_hh[HID * NG];   // [k][4*j+g]
__device__ float g_bp[NG];
__device__ float g_num[T_STEPS];
__device__ float g_den[T_STEPS];

__global__ void prep_kernel(const float* __restrict__ W_ih, const float* __restrict__ W_hh,
                            const float* __restrict__ b_ih, const float* __restrict__ b_hh)
{
    const int stride = gridDim.x * blockDim.x;
    const int tid0 = blockIdx.x * blockDim.x + threadIdx.x;
    for (int idx = tid0; idx < K_IH * NG; idx += stride) {
        int k = idx >> 8, col = idx & 255, j = col >> 2, g = col & 3;
        g_Wp_ih[idx] = W_ih[(g * 64 + j) * K_IH + k];
    }
    for (int idx = tid0; idx < HID * NG; idx += stride) {
        int k = idx >> 8, col = idx & 255, j = col >> 2, g = col & 3;
        g_Wp_hh[idx] = W_hh[(g * 64 + j) * HID + k];
    }
    for (int idx = tid0; idx < NG; idx += stride) {
        int j = idx >> 2, g = idx & 3;
        g_bp[idx] = b_ih[g * 64 + j] + b_hh[g * 64 + j];
    }
    for (int idx = tid0; idx < T_STEPS; idx += stride) {
        g_num[idx] = 0.f;
        g_den[idx] = 0.f;
    }
}

__device__ __forceinline__ float sigm(float x) { return 1.f / (1.f + __expf(-x)); }

__global__ __launch_bounds__(NTHR, 1) void main_kernel(
    const float* __restrict__ values, const float* __restrict__ masks,
    const float* __restrict__ deltas,
    const int* __restrict__ years, const int* __restrict__ months,
    const int* __restrict__ days, const int* __restrict__ hours,
    const float* __restrict__ em_year, const float* __restrict__ em_month,
    const float* __restrict__ em_day, const float* __restrict__ em_hour,
    const float* __restrict__ W_reg, const float* __restrict__ b_reg,
    const float* __restrict__ W_dec, const float* __restrict__ b_dec,
    float* __restrict__ out, int predOff)
{
    extern __shared__ float sm[];
    float* sS    = sm + S_OFF;
    float* sH    = sm + H_OFF;
    float* sDate = sm + DATE_OFF;
    float* sWr   = sm + WR_OFF;
    float* sWd   = sm + WD_OFF;
    float* sBreg = sm + BREG_OFF;
    float* sBdec = sm + BDEC_OFF;
    float* sEm   = sm + EM_OFF;
    float* sBp   = sm + BP_OFF;
    float* sNum  = sm + NUM_OFF;
    float* sDen  = sm + DEN_OFF;

    const int tid = threadIdx.x;
    const int e0  = blockIdx.x * BM;

    // ---- one-time SMEM init ----
    for (int i = tid; i < 74 * 36; i += NTHR) { int f = i / 74, k = i % 74; sWr[k * 36 + f] = W_reg[i]; }
    for (int i = tid; i < 36 * 36; i += NTHR) { int f = i / 36, k = i % 36; sWd[k * 36 + f] = W_dec[i]; }
    if (tid < 36)                    sBreg[tid] = b_reg[tid];
    if (tid >= 64 && tid < 100)      sBdec[tid - 64] = b_dec[tid - 64];
    if (tid >= 128 && tid < 132)     sEm[tid - 128] = em_year[tid - 128];
    if (tid >= 160 && tid < 184)     sEm[4 + tid - 160] = em_month[tid - 160];
    if (tid >= 192 && tid < 288)     sEm[28 + tid - 192] = em_day[tid - 192];
    if (tid >= 320 && tid < 392)     sEm[124 + tid - 320] = em_hour[tid - 320];
    if (tid >= 512 && tid < 768)     sBp[tid - 512] = g_bp[tid - 512];
    for (int i = tid; i < BM * HID; i += NTHR) sH[i] = 0.f;   // h buffer 0 = h_0
    if (tid >= 896 && tid < 932)     sNum[tid - 896] = 0.f;
    if (tid >= 960 && tid < 996)     sDen[tid - 960] = 0.f;
    __syncthreads();

    const int j    = tid & 63;   // hidden unit
    const int egrp = tid >> 6;   // 16 groups of 8 batch elements
    float c[8];
#pragma unroll
    for (int i = 0; i < 8; ++i) c[i] = 0.f;
    const float4 bp4 = *(const float4*)&sBp[4 * j];
    const float4* __restrict__ Wih4 = (const float4*)&g_Wp_ih[4 * j];  // stride NG/4 float4 per k
    const float4* __restrict__ Whh4 = (const float4*)&g_Wp_hh[4 * j];

    for (int t = 0; t < T_STEPS; ++t) {
        float* hin  = sH + (t & 1)       * (BM * HID);
        float* hout = sH + ((t + 1) & 1) * (BM * HID);

        // ---- date embedding gather ----
        if (tid < BM) {
            int bT = (e0 + tid) * T_STEPS + t;
            int yr = years[bT], mo = months[bT], dy = days[bT], hr = hours[bT];
            float* dd = &sDate[tid * 10];
            dd[0] = sEm[yr * 2];        dd[1] = sEm[yr * 2 + 1];
            dd[2] = sEm[4 + mo * 2];    dd[3] = sEm[4 + mo * 2 + 1];
            dd[4] = sEm[28 + dy * 3];   dd[5] = sEm[28 + dy * 3 + 1];  dd[6] = sEm[28 + dy * 3 + 2];
            dd[7] = sEm[124 + hr * 3];  dd[8] = sEm[124 + hr * 3 + 1]; dd[9] = sEm[124 + hr * 3 + 2];
        }
        __syncthreads();  // also orders prev-step phase B (h writes / S reads) before phase A

        // ---- Phase A: x_h, gamma, x_c, loss partials, predictions ----
        float lnum = 0.f, lden = 0.f;
        for (int idx = tid; idx < BM * FEAT; idx += NTHR) {
            int e = idx / FEAT, f = idx - e * FEAT;
            const float* dt = &sDate[e * 10];
            float a = sBreg[f];
#pragma unroll
            for (int k = 0; k < 10; ++k) a += dt[k] * sWr[k * 36 + f];
            const float4* hv = (const float4*)&hin[e * HID];
#pragma unroll 4
            for (int k4 = 0; k4 < 16; ++k4) {
                float4 h4 = hv[k4];
                a += h4.x * sWr[(10 + 4 * k4 + 0) * 36 + f];
                a += h4.y * sWr[(10 + 4 * k4 + 1) * 36 + f];
                a += h4.z * sWr[(10 + 4 * k4 + 2) * 36 + f];
                a += h4.w * sWr[(10 + 4 * k4 + 3) * 36 + f];
            }
            int base = ((e0 + e) * T_STEPS + t) * FEAT;
            float g = sBdec[f];
            const float4* dv = (const float4*)(deltas + base);
#pragma unroll 3
            for (int k4 = 0; k4 < 9; ++k4) {
                float4 d4 = dv[k4];
                g += d4.x * sWd[(4 * k4 + 0) * 36 + f];
                g += d4.y * sWd[(4 * k4 + 1) * 36 + f];
                g += d4.z * sWd[(4 * k4 + 2) * 36 + f];
                g += d4.w * sWd[(4 * k4 + 3) * 36 + f];
            }
            g = __expf(-fmaxf(g, 0.f));
            float x = values[base + f], m = masks[base + f];
            sS[e * 108 + f]      = m * x + (1.f - m) * a;  // x_c
            sS[e * 108 + 36 + f] = g;                      // gamma
            sS[e * 108 + 72 + f] = m;                      // m
            out[predOff + base + f] = a;                   // prediction
            lnum += fabsf(x - a) * m;
            lden += m;
        }
#pragma unroll
        for (int o = 16; o; o >>= 1) {
            lnum += __shfl_xor_sync(0xffffffffu, lnum, o);
            lden += __shfl_xor_sync(0xffffffffu, lden, o);
        }
        if ((tid & 31) == 0) { atomicAdd(&sNum[t], lnum); atomicAdd(&sDen[t], lden); }
        __syncthreads();  // S complete before gates GEMM

        // ---- Phase B: gates GEMM + LSTM update (two passes of 4 elems) ----
        for (int p = 0; p < 2; ++p) {
            const int eb = egrp * 8 + p * 4;
            float acc[4][4];
#pragma unroll
            for (int ei = 0; ei < 4; ++ei) {
                acc[ei][0] = bp4.x; acc[ei][1] = bp4.y; acc[ei][2] = bp4.z; acc[ei][3] = bp4.w;
            }
            {
                const float* s0 = &sS[(eb + 0) * 108];
                const float* s1 = &sS[(eb + 1) * 108];
                const float* s2 = &sS[(eb + 2) * 108];
                const float* s3 = &sS[(eb + 3) * 108];
#pragma unroll 1
                for (int k4 = 0; k4 < 27; ++k4) {
                    float4 a0 = *(const float4*)(s0 + 4 * k4);
                    float4 a1 = *(const float4*)(s1 + 4 * k4);
                    float4 a2 = *(const float4*)(s2 + 4 * k4);
                    float4 a3 = *(const float4*)(s3 + 4 * k4);
#pragma unroll
                    for (int kk = 0; kk < 4; ++kk) {
                        const float4 w = Wih4[(4 * k4 + kk) * (NG / 4)];
                        float v[4];
                        v[0] = ((const float*)&a0)[kk];
                        v[1] = ((const float*)&a1)[kk];
                        v[2] = ((const float*)&a2)[kk];
                        v[3] = ((const float*)&a3)[kk];
#pragma unroll
                        for (int ei = 0; ei < 4; ++ei) {
                            acc[ei][0] += v[ei] * w.x;
                            acc[ei][1] += v[ei] * w.y;
                            acc[ei][2] += v[ei] * w.z;
                            acc[ei][3] += v[ei] * w.w;
                        }
                    }
                }
            }
            {
                const float* h0 = &hin[(eb + 0) * HID];
                const float* h1 = &hin[(eb + 1) * HID];
                const float* h2 = &hin[(eb + 2) * HID];
                const float* h3 = &hin[(eb + 3) * HID];
#pragma unroll 1
                for (int k4 = 0; k4 < 16; ++k4) {
                    float4 a0 = *(const float4*)(h0 + 4 * k4);
                    float4 a1 = *(const float4*)(h1 + 4 * k4);
                    float4 a2 = *(const float4*)(h2 + 4 * k4);
                    float4 a3 = *(const float4*)(h3 + 4 * k4);
#pragma unroll
                    for (int kk = 0; kk < 4; ++kk) {
                        const float4 w = Whh4[(4 * k4 + kk) * (NG / 4)];
                        float v[4];
                        v[0] = ((const float*)&a0)[kk];
                        v[1] = ((const float*)&a1)[kk];
                        v[2] = ((const float*)&a2)[kk];
                        v[3] = ((const float*)&a3)[kk];
#pragma unroll
                        for (int ei = 0; ei < 4; ++ei) {
                            acc[ei][0] += v[ei] * w.x;
                            acc[ei][1] += v[ei] * w.y;
                            acc[ei][2] += v[ei] * w.z;
                            acc[ei][3] += v[ei] * w.w;
                        }
                    }
                }
            }
            // LSTM nonlinearity: gate order i, f, g, o
#pragma unroll
            for (int ei = 0; ei < 4; ++ei) {
                int li = p * 4 + ei;
                float ig = sigm(acc[ei][0]);
                float fg = sigm(acc[ei][1]);
                float gg = tanhf(acc[ei][2]);
                float og = sigm(acc[ei][3]);
                float cn = fg * c[li] + ig * gg;
                c[li] = cn;
                hout[(eb + ei) * HID + j] = og * tanhf(cn);
            }
        }
        // loop-top barrier (after date gather) orders phase B vs next phase A
    }

    __syncthreads();
    if (tid < T_STEPS) {
        atomicAdd(&g_num[tid], sNum[tid]);
        atomicAdd(&g_den[tid], sDen[tid]);
    }
}

__global__ void loss_kernel(float* __restrict__ out, int hasLoss)
{
    if (threadIdx.x == 0 && hasLoss) {
        float s = 0.f;
        for (int t = 0; t < T_STEPS; ++t) s += g_num[t] / g_den[t];
        out[0] = s / (float)T_STEPS;
    }
}

extern "C" void kernel_launch(void* const* d_in, const int* in_sizes, int n_in,
                              void* d_out, int out_size)
{
    const float* values     = (const float*)d_in[0];
    const float* masks      = (const float*)d_in[1];
    const float* deltas     = (const float*)d_in[2];
    // d_in[3] labels, d_in[4] label_masks: unused by the forward math
    const int*   years      = (const int*)d_in[5];
    const int*   months     = (const int*)d_in[6];
    const int*   days       = (const int*)d_in[7];
    const int*   hours      = (const int*)d_in[8];
    const float* em_year    = (const float*)d_in[9];
    const float* em_month   = (const float*)d_in[10];
    const float* em_day     = (const float*)d_in[11];
    const float* em_hour    = (const float*)d_in[12];
    const float* W_reg      = (const float*)d_in[13];
    const float* b_reg      = (const float*)d_in[14];
    const float* W_dec      = (const float*)d_in[15];
    const float* b_dec      = (const float*)d_in[16];
    const float* W_ih       = (const float*)d_in[17];
    const float* W_hh       = (const float*)d_in[18];
    const float* b_ih       = (const float*)d_in[19];
    const float* b_hh       = (const float*)d_in[20];

    float* out = (float*)d_out;
    const int Bn = in_sizes[0] / (T_STEPS * FEAT);
    const int N  = Bn * T_STEPS * FEAT;
    const int predOff = (out_size == N + 1) ? 1 : 0;

    cudaFuncSetAttribute(main_kernel, cudaFuncAttributeMaxDynamicSharedMemorySize, SMEM_BYTES);

    prep_kernel<<<64, 256>>>(W_ih, W_hh, b_ih, b_hh);
    main_kernel<<<Bn / BM, NTHR, SMEM_BYTES>>>(
        values, masks, deltas, years, months, days, hours,
        em_year, em_month, em_day, em_hour,
        W_reg, b_reg, W_dec, b_dec, out, predOff);
    loss_kernel<<<1, 32>>>(out, predOff);
}

// round 3
// speedup vs baseline: 1.2589x; 1.2589x over previous
#include <cuda_runtime.h>

#define T_STEPS 36
#define FEAT 36
#define HID 64
#define NG 256
#define K_IH 108
#define BM 128
#define NTHR 1024
#define RS 132              // transposed-row stride (floats): 528B, 16B-aligned

// SMEM layout (float offsets)
#define ST_OFF   0                         // S_T[108][RS] : rows 0-35 x_c, 36-71 gamma, 72-107 m
#define HT_OFF   (ST_OFF + 108 * RS)       // h_T[2][64][RS]
#define HL_OFF   (HT_OFF + 2 * 64 * RS)    // h_lin[128][64] (single buffer)
#define DATE_OFF (HL_OFF + BM * HID)       // date[128][10]
#define WR_OFF   (DATE_OFF + BM * 10)      // Wr[74][36] k-major
#define WD_OFF   (WR_OFF + 74 * 36)        // Wd[36][36] k-major
#define BREG_OFF (WD_OFF + 36 * 36)
#define BDEC_OFF (BREG_OFF + 36)
#define EM_OFF   (BDEC_OFF + 36)           // year(4) month(24) day(96) hour(72)
#define BP_OFF   (EM_OFF + 196)            // permuted b_ih+b_hh [256]
#define NUM_OFF  (BP_OFF + 256)
#define DEN_OFF  (NUM_OFF + 36)
#define SMEM_FLOATS (DEN_OFF + 36)
#define SMEM_BYTES (SMEM_FLOATS * 4)

typedef unsigned long long ull;

// Global scratch — permuted gate weights [k][4*j+g] + loss accumulators
__device__ __align__(16) float g_Wp_ih[K_IH * NG];
__device__ __align__(16) float g_Wp_hh[HID * NG];
__device__ float g_bp[NG];
__device__ float g_num[T_STEPS];
__device__ float g_den[T_STEPS];

__global__ void prep_kernel(const float* __restrict__ W_ih, const float* __restrict__ W_hh,
                            const float* __restrict__ b_ih, const float* __restrict__ b_hh)
{
    const int stride = gridDim.x * blockDim.x;
    const int tid0 = blockIdx.x * blockDim.x + threadIdx.x;
    for (int idx = tid0; idx < K_IH * NG; idx += stride) {
        int k = idx >> 8, col = idx & 255, j = col >> 2, g = col & 3;
        g_Wp_ih[idx] = W_ih[(g * 64 + j) * K_IH + k];
    }
    for (int idx = tid0; idx < HID * NG; idx += stride) {
        int k = idx >> 8, col = idx & 255, j = col >> 2, g = col & 3;
        g_Wp_hh[idx] = W_hh[(g * 64 + j) * HID + k];
    }
    for (int idx = tid0; idx < NG; idx += stride) {
        int j = idx >> 2, g = idx & 3;
        g_bp[idx] = b_ih[g * 64 + j] + b_hh[g * 64 + j];
    }
    for (int idx = tid0; idx < T_STEPS; idx += stride) {
        g_num[idx] = 0.f;
        g_den[idx] = 0.f;
    }
}

__device__ __forceinline__ float sigm(float x) { return 1.f / (1.f + __expf(-x)); }

__device__ __forceinline__ ull pk2(float a) {
    ull r; asm("mov.b64 %0, {%1, %1};" : "=l"(r) : "f"(a)); return r;
}
__device__ __forceinline__ void upk(ull v, float& lo, float& hi) {
    asm("mov.b64 {%0, %1}, %2;" : "=f"(lo), "=f"(hi) : "l"(v));
}
__device__ __forceinline__ void fma2(ull& d, ull a, ull b) {
    asm("fma.rn.f32x2 %0, %1, %2, %0;" : "+l"(d) : "l"(a), "l"(b));
}

__global__ __launch_bounds__(NTHR, 1) void main_kernel(
    const float* __restrict__ values, const float* __restrict__ masks,
    const float* __restrict__ deltas,
    const int* __restrict__ years, const int* __restrict__ months,
    const int* __restrict__ days, const int* __restrict__ hours,
    const float* __restrict__ em_year, const float* __restrict__ em_month,
    const float* __restrict__ em_day, const float* __restrict__ em_hour,
    const float* __restrict__ W_reg, const float* __restrict__ b_reg,
    const float* __restrict__ W_dec, const float* __restrict__ b_dec,
    float* __restrict__ out, int predOff)
{
    extern __shared__ float sm[];
    float* sST   = sm + ST_OFF;
    float* sHT   = sm + HT_OFF;
    float* sHL   = sm + HL_OFF;
    float* sDate = sm + DATE_OFF;
    float* sWr   = sm + WR_OFF;
    float* sWd   = sm + WD_OFF;
    float* sBreg = sm + BREG_OFF;
    float* sBdec = sm + BDEC_OFF;
    float* sEm   = sm + EM_OFF;
    float* sBp   = sm + BP_OFF;
    float* sNum  = sm + NUM_OFF;
    float* sDen  = sm + DEN_OFF;

    const int tid = threadIdx.x;
    const int e0  = blockIdx.x * BM;

    // ---- one-time SMEM init ----
    for (int i = tid; i < 74 * 36; i += NTHR) { int f = i / 74, k = i % 74; sWr[k * 36 + f] = W_reg[i]; }
    for (int i = tid; i < 36 * 36; i += NTHR) { int f = i / 36, k = i % 36; sWd[k * 36 + f] = W_dec[i]; }
    if (tid < 36)                    sBreg[tid] = b_reg[tid];
    if (tid >= 64 && tid < 100)      sBdec[tid - 64] = b_dec[tid - 64];
    if (tid >= 128 && tid < 132)     sEm[tid - 128] = em_year[tid - 128];
    if (tid >= 160 && tid < 184)     sEm[4 + tid - 160] = em_month[tid - 160];
    if (tid >= 192 && tid < 288)     sEm[28 + tid - 192] = em_day[tid - 192];
    if (tid >= 320 && tid < 392)     sEm[124 + tid - 320] = em_hour[tid - 320];
    if (tid >= 512 && tid < 768)     sBp[tid - 512] = g_bp[tid - 512];
    for (int i = tid; i < 2 * 64 * RS; i += NTHR) sHT[i] = 0.f;   // h_T both buffers = 0
    for (int i = tid; i < BM * HID; i += NTHR)    sHL[i] = 0.f;   // h_lin = 0
    if (tid >= 896 && tid < 932)     sNum[tid - 896] = 0.f;
    if (tid >= 960 && tid < 996)     sDen[tid - 960] = 0.f;
    __syncthreads();

    const int j   = tid & 63;        // hidden unit (gate column group 4j..4j+3)
    const int eg8 = (tid >> 6) * 8;  // first of 8 owned batch elems
    float c[8];
#pragma unroll
    for (int i = 0; i < 8; ++i) c[i] = 0.f;
    const float4 bp4 = *(const float4*)&sBp[4 * j];
    const float4* __restrict__ Wih4 = (const float4*)&g_Wp_ih[4 * j];  // stride NG/4 float4 per k
    const float4* __restrict__ Whh4 = (const float4*)&g_Wp_hh[4 * j];

    for (int t = 0; t < T_STEPS; ++t) {
        const int tb = t & 1;
        float* hTin  = sHT + tb * (64 * RS);
        float* hTout = sHT + (tb ^ 1) * (64 * RS);

        // ---- date embedding gather ----
        if (tid < BM) {
            int bT = (e0 + tid) * T_STEPS + t;
            int yr = years[bT], mo = months[bT], dy = days[bT], hr = hours[bT];
            float* dd = &sDate[tid * 10];
            dd[0] = sEm[yr * 2];        dd[1] = sEm[yr * 2 + 1];
            dd[2] = sEm[4 + mo * 2];    dd[3] = sEm[4 + mo * 2 + 1];
            dd[4] = sEm[28 + dy * 3];   dd[5] = sEm[28 + dy * 3 + 1];  dd[6] = sEm[28 + dy * 3 + 2];
            dd[7] = sEm[124 + hr * 3];  dd[8] = sEm[124 + hr * 3 + 1]; dd[9] = sEm[124 + hr * 3 + 2];
        }
        __syncthreads();  // orders prev Phase B (h writes) + date before Phase A

        // ---- Phase A: x_h, gamma, x_c, loss partials, predictions ----
        float lnum = 0.f, lden = 0.f;
        for (int idx = tid; idx < BM * FEAT; idx += NTHR) {
            int e = idx / FEAT, f = idx - e * FEAT;
            const float* dt = &sDate[e * 10];
            float a = sBreg[f];
#pragma unroll
            for (int k = 0; k < 10; ++k) a += dt[k] * sWr[k * 36 + f];
            const float4* hv = (const float4*)&sHL[e * HID];
#pragma unroll 4
            for (int k4 = 0; k4 < 16; ++k4) {
                float4 h4 = hv[k4];
                a += h4.x * sWr[(10 + 4 * k4 + 0) * 36 + f];
                a += h4.y * sWr[(10 + 4 * k4 + 1) * 36 + f];
                a += h4.z * sWr[(10 + 4 * k4 + 2) * 36 + f];
                a += h4.w * sWr[(10 + 4 * k4 + 3) * 36 + f];
            }
            int base = ((e0 + e) * T_STEPS + t) * FEAT;
            float g = sBdec[f];
            const float4* dv = (const float4*)(deltas + base);
#pragma unroll 3
            for (int k4 = 0; k4 < 9; ++k4) {
                float4 d4 = dv[k4];
                g += d4.x * sWd[(4 * k4 + 0) * 36 + f];
                g += d4.y * sWd[(4 * k4 + 1) * 36 + f];
                g += d4.z * sWd[(4 * k4 + 2) * 36 + f];
                g += d4.w * sWd[(4 * k4 + 3) * 36 + f];
            }
            g = __expf(-fmaxf(g, 0.f));
            float x = values[base + f], m = masks[base + f];
            sST[f * RS + e]         = m * x + (1.f - m) * a;  // x_c (transposed)
            sST[(36 + f) * RS + e]  = g;                      // gamma
            sST[(72 + f) * RS + e]  = m;                      // m
            out[predOff + base + f] = a;                      // prediction
            lnum += fabsf(x - a) * m;
            lden += m;
        }
#pragma unroll
        for (int o = 16; o; o >>= 1) {
            lnum += __shfl_xor_sync(0xffffffffu, lnum, o);
            lden += __shfl_xor_sync(0xffffffffu, lden, o);
        }
        if ((tid & 31) == 0) { atomicAdd(&sNum[t], lnum); atomicAdd(&sDen[t], lden); }
        __syncthreads();  // S_T complete before gates GEMM

        // ---- Phase B: gates GEMM (f32x2 packed, batch pairs), single 8-elem pass ----
        {
            ull acc[16];  // [pair p 0..3][gate g 0..3] ; each = (elem eg8+2p, eg8+2p+1)
#pragma unroll
            for (int p = 0; p < 4; ++p) {
                acc[4 * p + 0] = pk2(bp4.x); acc[4 * p + 1] = pk2(bp4.y);
                acc[4 * p + 2] = pk2(bp4.z); acc[4 * p + 3] = pk2(bp4.w);
            }
            const float* sTb = sST + eg8;
#pragma unroll 2
            for (int k = 0; k < K_IH; ++k) {
                float4 w = Wih4[k * (NG / 4)];
                ulonglong2 vA = *(const ulonglong2*)(sTb + k * RS);       // pairs 0,1 (broadcast)
                ulonglong2 vB = *(const ulonglong2*)(sTb + k * RS + 4);   // pairs 2,3
                ull wd;
                wd = pk2(w.x); fma2(acc[0], vA.x, wd); fma2(acc[4], vA.y, wd); fma2(acc[8],  vB.x, wd); fma2(acc[12], vB.y, wd);
                wd = pk2(w.y); fma2(acc[1], vA.x, wd); fma2(acc[5], vA.y, wd); fma2(acc[9],  vB.x, wd); fma2(acc[13], vB.y, wd);
                wd = pk2(w.z); fma2(acc[2], vA.x, wd); fma2(acc[6], vA.y, wd); fma2(acc[10], vB.x, wd); fma2(acc[14], vB.y, wd);
                wd = pk2(w.w); fma2(acc[3], vA.x, wd); fma2(acc[7], vA.y, wd); fma2(acc[11], vB.x, wd); fma2(acc[15], vB.y, wd);
            }
            const float* hTb = hTin + eg8;
#pragma unroll 2
            for (int k = 0; k < HID; ++k) {
                float4 w = Whh4[k * (NG / 4)];
                ulonglong2 vA = *(const ulonglong2*)(hTb + k * RS);
                ulonglong2 vB = *(const ulonglong2*)(hTb + k * RS + 4);
                ull wd;
                wd = pk2(w.x); fma2(acc[0], vA.x, wd); fma2(acc[4], vA.y, wd); fma2(acc[8],  vB.x, wd); fma2(acc[12], vB.y, wd);
                wd = pk2(w.y); fma2(acc[1], vA.x, wd); fma2(acc[5], vA.y, wd); fma2(acc[9],  vB.x, wd); fma2(acc[13], vB.y, wd);
                wd = pk2(w.z); fma2(acc[2], vA.x, wd); fma2(acc[6], vA.y, wd); fma2(acc[10], vB.x, wd); fma2(acc[14], vB.y, wd);
                wd = pk2(w.w); fma2(acc[3], vA.x, wd); fma2(acc[7], vA.y, wd); fma2(acc[11], vB.x, wd); fma2(acc[15], vB.y, wd);
            }
            // LSTM nonlinearity (gate order i, f, g, o); write h both layouts
#pragma unroll
            for (int p = 0; p < 4; ++p) {
                float i0, i1, f0, f1, g0, g1, o0, o1;
                upk(acc[4 * p + 0], i0, i1);
                upk(acc[4 * p + 1], f0, f1);
                upk(acc[4 * p + 2], g0, g1);
                upk(acc[4 * p + 3], o0, o1);
                int e = eg8 + 2 * p;
                float cn0 = sigm(f0) * c[2 * p]     + sigm(i0) * tanhf(g0);
                float cn1 = sigm(f1) * c[2 * p + 1] + sigm(i1) * tanhf(g1);
                c[2 * p] = cn0; c[2 * p + 1] = cn1;
                float h0 = sigm(o0) * tanhf(cn0);
                float h1 = sigm(o1) * tanhf(cn1);
                sHL[e * HID + j]       = h0;
                sHL[(e + 1) * HID + j] = h1;
                hTout[j * RS + e]      = h0;
                hTout[j * RS + e + 1]  = h1;
            }
        }
        // loop-top barrier orders Phase B writes vs next Phase A reads
    }

    __syncthreads();
    if (tid < T_STEPS) {
        atomicAdd(&g_num[tid], sNum[tid]);
        atomicAdd(&g_den[tid], sDen[tid]);
    }
}

__global__ void loss_kernel(float* __restrict__ out, int hasLoss)
{
    if (threadIdx.x == 0 && hasLoss) {
        float s = 0.f;
        for (int t = 0; t < T_STEPS; ++t) s += g_num[t] / g_den[t];
        out[0] = s / (float)T_STEPS;
    }
}

extern "C" void kernel_launch(void* const* d_in, const int* in_sizes, int n_in,
                              void* d_out, int out_size)
{
    const float* values     = (const float*)d_in[0];
    const float* masks      = (const float*)d_in[1];
    const float* deltas     = (const float*)d_in[2];
    // d_in[3] labels, d_in[4] label_masks: unused by the forward math
    const int*   years      = (const int*)d_in[5];
    const int*   months     = (const int*)d_in[6];
    const int*   days       = (const int*)d_in[7];
    const int*   hours      = (const int*)d_in[8];
    const float* em_year    = (const float*)d_in[9];
    const float* em_month   = (const float*)d_in[10];
    const float* em_day     = (const float*)d_in[11];
    const float* em_hour    = (const float*)d_in[12];
    const float* W_reg      = (const float*)d_in[13];
    const float* b_reg      = (const float*)d_in[14];
    const float* W_dec      = (const float*)d_in[15];
    const float* b_dec      = (const float*)d_in[16];
    const float* W_ih       = (const float*)d_in[17];
    const float* W_hh       = (const float*)d_in[18];
    const float* b_ih       = (const float*)d_in[19];
    const float* b_hh       = (const float*)d_in[20];

    float* out = (float*)d_out;
    const int Bn = in_sizes[0] / (T_STEPS * FEAT);
    const int N  = Bn * T_STEPS * FEAT;
    const int predOff = (out_size == N + 1) ? 1 : 0;

    cudaFuncSetAttribute(main_kernel, cudaFuncAttributeMaxDynamicSharedMemorySize, SMEM_BYTES);

    prep_kernel<<<64, 256>>>(W_ih, W_hh, b_ih, b_hh);
    main_kernel<<<Bn / BM, NTHR, SMEM_BYTES>>>(
        values, masks, deltas, years, months, days, hours,
        em_year, em_month, em_day, em_hour,
        W_reg, b_reg, W_dec, b_dec, out, predOff);
    loss_kernel<<<1, 32>>>(out, predOff);
}